// round 15
// baseline (speedup 1.0000x reference)
#include <cuda_runtime.h>
#include <cstdint>

// EmbeddingBag mode='sum'. No cache hints (R5/R7/R11: eviction policies are
// neutral-to-harmful on this uniform-random access pattern).
//   out[b][:] = sum_{i in [offsets[b], offsets[b+1])} W[indices[i]][:]
//
// Warp per bag. float4 per lane: grp = lane>>4 selects one of 2 rows per
// warp-load, sub = lane&15 selects the 16B slice (16 lanes x 16B = 256B row).
// Main loop consumes 16 indices per iteration via 8 independent LDG.128
// (16 rows, 32 lines statically in flight per warp); all 8 index loads are
// front-batched before the row loads so the gather批 issues back-to-back.
// Testing: is 5.1TB/s a latency gap (this helps) or the random-256B HBM
// page-efficiency wall (this is neutral)?
// Reduction: one shfl.xor(16); lanes 0-15 store one float4 each.

#define EMB_DIM 64
#define F4_PER_ROW (EMB_DIM / 4)   // 16 float4 per row

__global__ __launch_bounds__(256) void embag_sum_kernel(
    const float4* __restrict__ W4,
    const int*    __restrict__ indices,
    const int*    __restrict__ offsets,
    float4*       __restrict__ out4,
    int n_idx,
    int n_bags)
{
    const int warp = (blockIdx.x * blockDim.x + threadIdx.x) >> 5;
    const int lane = threadIdx.x & 31;
    const int grp  = lane >> 4;    // 0..1: which row within a 2-pack
    const int sub  = lane & 15;    // 0..15: which 16B slice of the row
    if (warp >= n_bags) return;

    const int start = __ldg(&offsets[warp]);
    const int end   = (warp + 1 < n_bags) ? __ldg(&offsets[warp + 1]) : n_idx;

    float4 acc[4];
    #pragma unroll
    for (int k = 0; k < 4; ++k) acc[k] = make_float4(0.f, 0.f, 0.f, 0.f);

    int i = start;
    // Main loop: 16 indices per iteration via 8 independent 128-bit loads.
    for (; i + 16 <= end; i += 16) {
        int r[8];
        #pragma unroll
        for (int k = 0; k < 8; ++k)
            r[k] = __ldg(&indices[i + 2 * k + grp]);

        float4 v[8];
        #pragma unroll
        for (int k = 0; k < 8; ++k)
            v[k] = __ldg(&W4[(size_t)r[k] * F4_PER_ROW + sub]);

        #pragma unroll
        for (int k = 0; k < 8; ++k) {
            acc[k & 3].x += v[k].x;
            acc[k & 3].y += v[k].y;
            acc[k & 3].z += v[k].z;
            acc[k & 3].w += v[k].w;
        }
    }
    // Pair tail: 2 indices at a time (one warp-load).
    for (; i + 2 <= end; i += 2) {
        const int r = __ldg(&indices[i + grp]);
        const float4 v = __ldg(&W4[(size_t)r * F4_PER_ROW + sub]);
        acc[0].x += v.x; acc[0].y += v.y; acc[0].z += v.z; acc[0].w += v.w;
    }
    // Ragged single index: only group 0 participates.
    if (i < end && grp == 0) {
        const int r = __ldg(&indices[i]);
        const float4 v = __ldg(&W4[(size_t)r * F4_PER_ROW + sub]);
        acc[1].x += v.x; acc[1].y += v.y; acc[1].z += v.z; acc[1].w += v.w;
    }

    float4 a;
    a.x = (acc[0].x + acc[1].x) + (acc[2].x + acc[3].x);
    a.y = (acc[0].y + acc[1].y) + (acc[2].y + acc[3].y);
    a.z = (acc[0].z + acc[1].z) + (acc[2].z + acc[3].z);
    a.w = (acc[0].w + acc[1].w) + (acc[2].w + acc[3].w);

    // Fold the two lane-groups: partner lane is lane^16.
    a.x += __shfl_xor_sync(0xFFFFFFFFu, a.x, 16);
    a.y += __shfl_xor_sync(0xFFFFFFFFu, a.y, 16);
    a.z += __shfl_xor_sync(0xFFFFFFFFu, a.z, 16);
    a.w += __shfl_xor_sync(0xFFFFFFFFu, a.w, 16);

    // Lanes 0-15 hold the bag sum for dims [sub*4, sub*4+4).
    if (lane < 16) {
        out4[(size_t)warp * F4_PER_ROW + sub] = a;
    }
}

extern "C" void kernel_launch(void* const* d_in, const int* in_sizes, int n_in,
                              void* d_out, int out_size)
{
    const float4* W4      = (const float4*)d_in[0];
    const int*    indices = (const int*)d_in[1];
    const int*    offsets = (const int*)d_in[2];
    float4*       out4    = (float4*)d_out;

    const int n_idx  = in_sizes[1];
    const int n_bags = in_sizes[2];

    const int warps_per_block = 256 / 32;
    const int blocks = (n_bags + warps_per_block - 1) / warps_per_block;

    embag_sum_kernel<<<blocks, 256>>>(W4, indices, offsets, out4, n_idx, n_bags);
}

// round 16
// speedup vs baseline: 1.0491x; 1.0491x over previous
#include <cuda_runtime.h>
#include <cstdint>

// EmbeddingBag mode='sum'.
//   out[b][:] = sum_{i in [offsets[b], offsets[b+1])} W[indices[i]][:]
//
// TWO warps per bag, split by dimension half: warp h sums dims [h*32,h*32+32)
// (the h-th 128B line of every row). No atomics needed; each 128B line is
// fetched exactly once chip-wide. Doubling the warp count (32768) deepens the
// wave structure (3.46 waves at 8 blocks/SM vs 1.73) so the partial-wave
// occupancy loss shrinks -- R3/R7/R13/R15 established DRAM busy tracks
// achieved occupancy and regs must stay <=32.
//
// Lane layout: grp = lane>>3 picks one of 4 indices per warp-load, sub =
// lane&7 picks the 16B slice (8 lanes x 16B = 128B half-row). Main loop:
// 16 indices/iter via 4 front-batched LDG.128 (16 lines in flight/warp).
// Reduction: shfl.xor(8), shfl.xor(16); lanes 0-7 store one float4.

#define EMB_DIM 64
#define F4_PER_ROW (EMB_DIM / 4)   // 16 float4 per row

__global__ __launch_bounds__(256) void embag_sum_kernel(
    const float4* __restrict__ W4,
    const int*    __restrict__ indices,
    const int*    __restrict__ offsets,
    float4*       __restrict__ out4,
    int n_idx,
    int n_bags)
{
    const int gwarp = (blockIdx.x * blockDim.x + threadIdx.x) >> 5;
    const int lane  = threadIdx.x & 31;
    const int bag   = gwarp >> 1;
    const int half  = gwarp & 1;          // which 128B line of each row
    const int grp   = lane >> 3;          // 0..3: which index in a 4-pack
    const int sub   = lane & 7;           // 0..7: 16B slice within half-row
    if (bag >= n_bags) return;

    const int start = __ldg(&offsets[bag]);
    const int end   = (bag + 1 < n_bags) ? __ldg(&offsets[bag + 1]) : n_idx;

    // Column offset of this warp's half-row slice within a row (in float4).
    const int col = half * 8 + sub;

    float4 accA = make_float4(0.f, 0.f, 0.f, 0.f);
    float4 accB = make_float4(0.f, 0.f, 0.f, 0.f);

    int i = start;
    // Main loop: 16 indices per iteration, 4 independent LDG.128 (4 lines ea).
    for (; i + 16 <= end; i += 16) {
        const int r0 = __ldg(&indices[i      + grp]);
        const int r1 = __ldg(&indices[i +  4 + grp]);
        const int r2 = __ldg(&indices[i +  8 + grp]);
        const int r3 = __ldg(&indices[i + 12 + grp]);

        const float4 v0 = __ldg(&W4[(size_t)r0 * F4_PER_ROW + col]);
        const float4 v1 = __ldg(&W4[(size_t)r1 * F4_PER_ROW + col]);
        const float4 v2 = __ldg(&W4[(size_t)r2 * F4_PER_ROW + col]);
        const float4 v3 = __ldg(&W4[(size_t)r3 * F4_PER_ROW + col]);

        accA.x += v0.x; accA.y += v0.y; accA.z += v0.z; accA.w += v0.w;
        accB.x += v1.x; accB.y += v1.y; accB.z += v1.z; accB.w += v1.w;
        accA.x += v2.x; accA.y += v2.y; accA.z += v2.z; accA.w += v2.w;
        accB.x += v3.x; accB.y += v3.y; accB.z += v3.z; accB.w += v3.w;
    }
    // 4-wide tail (one warp-load each).
    for (; i + 4 <= end; i += 4) {
        const int r = __ldg(&indices[i + grp]);
        const float4 v = __ldg(&W4[(size_t)r * F4_PER_ROW + col]);
        accA.x += v.x; accA.y += v.y; accA.z += v.z; accA.w += v.w;
    }
    // Ragged tail (0..3 indices): group-predicated.
    {
        const int rem = end - i;
        if (grp < rem) {
            const int r = __ldg(&indices[i + grp]);
            const float4 v = __ldg(&W4[(size_t)r * F4_PER_ROW + col]);
            accB.x += v.x; accB.y += v.y; accB.z += v.z; accB.w += v.w;
        }
    }

    float4 a;
    a.x = accA.x + accB.x;
    a.y = accA.y + accB.y;
    a.z = accA.z + accB.z;
    a.w = accA.w + accB.w;

    // Fold the 4 lane-groups (partners at lane^8, lane^16).
    a.x += __shfl_xor_sync(0xFFFFFFFFu, a.x, 8);
    a.y += __shfl_xor_sync(0xFFFFFFFFu, a.y, 8);
    a.z += __shfl_xor_sync(0xFFFFFFFFu, a.z, 8);
    a.w += __shfl_xor_sync(0xFFFFFFFFu, a.w, 8);
    a.x += __shfl_xor_sync(0xFFFFFFFFu, a.x, 16);
    a.y += __shfl_xor_sync(0xFFFFFFFFu, a.y, 16);
    a.z += __shfl_xor_sync(0xFFFFFFFFu, a.z, 16);
    a.w += __shfl_xor_sync(0xFFFFFFFFu, a.w, 16);

    // Lanes 0-7 hold this half-row's bag sum; store one float4 each.
    if (lane < 8) {
        out4[(size_t)bag * F4_PER_ROW + col] = a;
    }
}

extern "C" void kernel_launch(void* const* d_in, const int* in_sizes, int n_in,
                              void* d_out, int out_size)
{
    const float4* W4      = (const float4*)d_in[0];
    const int*    indices = (const int*)d_in[1];
    const int*    offsets = (const int*)d_in[2];
    float4*       out4    = (float4*)d_out;

    const int n_idx  = in_sizes[1];
    const int n_bags = in_sizes[2];

    // Two warps per bag.
    const int n_warps = n_bags * 2;
    const int warps_per_block = 256 / 32;
    const int blocks = (n_warps + warps_per_block - 1) / warps_per_block;

    embag_sum_kernel<<<blocks, 256>>>(W4, indices, offsets, out4, n_idx, n_bags);
}

// round 17
// speedup vs baseline: 1.1168x; 1.0645x over previous
#include <cuda_runtime.h>
#include <cstdint>

// EmbeddingBag mode='sum'.
//   out[b][:] = sum_{i in [offsets[b], offsets[b+1])} W[indices[i]][:]
//
// R13 champion layout (warp per bag; 16-lane group per row; float4/lane;
// 8 indices per iteration via 4 independent LDG.128) plus:
//  * software-pipelined index loads: next iteration's 4 indices are loaded
//    BEFORE this iteration's row loads, so the idx->row serial chain
//    (L2 ~234cyc + DRAM ~600cyc) collapses to row latency only and row
//    loads issue back-to-back across iterations (sustained MLP ~16, not ~11).
//  * single float4 accumulator (frees 4 regs to pay for the prefetch regs;
//    the FADD chain is 32cyc/iter, irrelevant vs the 600cyc load wait).
//  * __stcs streaming stores for the write-once output (don't spend L2 ways).

#define EMB_DIM 64
#define F4_PER_ROW (EMB_DIM / 4)   // 16 float4 per row

__global__ __launch_bounds__(256) void embag_sum_kernel(
    const float4* __restrict__ W4,
    const int*    __restrict__ indices,
    const int*    __restrict__ offsets,
    float4*       __restrict__ out4,
    int n_idx,
    int n_bags)
{
    const int warp = (blockIdx.x * blockDim.x + threadIdx.x) >> 5;
    const int lane = threadIdx.x & 31;
    const int grp  = lane >> 4;    // 0..1: which row within a 2-pack
    const int sub  = lane & 15;    // 0..15: which 16B slice of the row
    if (warp >= n_bags) return;

    const int start = __ldg(&offsets[warp]);
    const int end   = (warp + 1 < n_bags) ? __ldg(&offsets[warp + 1]) : n_idx;

    float4 acc = make_float4(0.f, 0.f, 0.f, 0.f);

    int i = start;
    int r0 = 0, r1 = 0, r2 = 0, r3 = 0;
    if (i + 8 <= end) {            // prologue: indices for the first 8-pack
        r0 = __ldg(&indices[i + 0 + grp]);
        r1 = __ldg(&indices[i + 2 + grp]);
        r2 = __ldg(&indices[i + 4 + grp]);
        r3 = __ldg(&indices[i + 6 + grp]);
    }

    // Main loop: rows for pack p, indices prefetched for pack p+1.
    for (; i + 16 <= end; i += 8) {
        const int n0 = __ldg(&indices[i +  8 + grp]);
        const int n1 = __ldg(&indices[i + 10 + grp]);
        const int n2 = __ldg(&indices[i + 12 + grp]);
        const int n3 = __ldg(&indices[i + 14 + grp]);

        const float4 v0 = __ldg(&W4[(size_t)r0 * F4_PER_ROW + sub]);
        const float4 v1 = __ldg(&W4[(size_t)r1 * F4_PER_ROW + sub]);
        const float4 v2 = __ldg(&W4[(size_t)r2 * F4_PER_ROW + sub]);
        const float4 v3 = __ldg(&W4[(size_t)r3 * F4_PER_ROW + sub]);

        acc.x += v0.x; acc.y += v0.y; acc.z += v0.z; acc.w += v0.w;
        acc.x += v1.x; acc.y += v1.y; acc.z += v1.z; acc.w += v1.w;
        acc.x += v2.x; acc.y += v2.y; acc.z += v2.z; acc.w += v2.w;
        acc.x += v3.x; acc.y += v3.y; acc.z += v3.z; acc.w += v3.w;

        r0 = n0; r1 = n1; r2 = n2; r3 = n3;
    }
    // Epilogue: last full 8-pack (indices already in r0..r3).
    if (i + 8 <= end) {
        const float4 v0 = __ldg(&W4[(size_t)r0 * F4_PER_ROW + sub]);
        const float4 v1 = __ldg(&W4[(size_t)r1 * F4_PER_ROW + sub]);
        const float4 v2 = __ldg(&W4[(size_t)r2 * F4_PER_ROW + sub]);
        const float4 v3 = __ldg(&W4[(size_t)r3 * F4_PER_ROW + sub]);
        acc.x += v0.x; acc.y += v0.y; acc.z += v0.z; acc.w += v0.w;
        acc.x += v1.x; acc.y += v1.y; acc.z += v1.z; acc.w += v1.w;
        acc.x += v2.x; acc.y += v2.y; acc.z += v2.z; acc.w += v2.w;
        acc.x += v3.x; acc.y += v3.y; acc.z += v3.z; acc.w += v3.w;
        i += 8;
    }
    // Pair tail: 2 indices at a time (one warp-load).
    for (; i + 2 <= end; i += 2) {
        const int r = __ldg(&indices[i + grp]);
        const float4 v = __ldg(&W4[(size_t)r * F4_PER_ROW + sub]);
        acc.x += v.x; acc.y += v.y; acc.z += v.z; acc.w += v.w;
    }
    // Ragged single index: only group 0 participates.
    if (i < end && grp == 0) {
        const int r = __ldg(&indices[i]);
        const float4 v = __ldg(&W4[(size_t)r * F4_PER_ROW + sub]);
        acc.x += v.x; acc.y += v.y; acc.z += v.z; acc.w += v.w;
    }

    // Fold the two lane-groups: partner lane is lane^16.
    acc.x += __shfl_xor_sync(0xFFFFFFFFu, acc.x, 16);
    acc.y += __shfl_xor_sync(0xFFFFFFFFu, acc.y, 16);
    acc.z += __shfl_xor_sync(0xFFFFFFFFu, acc.z, 16);
    acc.w += __shfl_xor_sync(0xFFFFFFFFu, acc.w, 16);

    // Lanes 0-15 hold the bag sum for dims [sub*4, sub*4+4).
    // Streaming store: output is write-once, keep L2 for the table.
    if (lane < 16) {
        __stcs(&out4[(size_t)warp * F4_PER_ROW + sub], acc);
    }
}

extern "C" void kernel_launch(void* const* d_in, const int* in_sizes, int n_in,
                              void* d_out, int out_size)
{
    const float4* W4      = (const float4*)d_in[0];
    const int*    indices = (const int*)d_in[1];
    const int*    offsets = (const int*)d_in[2];
    float4*       out4    = (float4*)d_out;

    const int n_idx  = in_sizes[1];
    const int n_bags = in_sizes[2];

    const int warps_per_block = 256 / 32;
    const int blocks = (n_bags + warps_per_block - 1) / warps_per_block;

    embag_sum_kernel<<<blocks, 256>>>(W4, indices, offsets, out4, n_idx, n_bags);
}